// round 3
// baseline (speedup 1.0000x reference)
#include <cuda_runtime.h>

// Problem constants
#define BB 16
#define NL 4097          // x0 rows per batch (= 1+N_S too)
#define NM 1024          // p_m rows
#define DS 256
#define DM 512
#define DL 1024
#define NKV 4098         // cls + NL
#define MCH 32           // m-chunks for transposed gemv
#define CROWS 16         // rows per smem chunk in big kernel
#define CPB 8            // chunks per block
#define BCH 33           // ceil(NL / (CROWS*CPB))

// ---------------- device scratch ----------------
__device__ float g_csp  [BB*DM];
__device__ float g_q1   [BB*DM];
__device__ float g_qk1  [BB*DM];
__device__ float g_cmp  [BB*DL];
__device__ float g_q2   [BB*DL];
__device__ float g_qk2  [BB*DL];
__device__ float g_sc1  [BB*(NM+1)];
__device__ float g_att1s[BB*(NM+1)];
__device__ float g_a1p  [BB*NKV];
__device__ float g_PE   [BB*BCH*DL];
__device__ float g_PA   [BB*BCH*DL];
__device__ float g_PZ   [BB*BCH];
__device__ float g_u    [BB*DL];
__device__ float g_outv [BB*DL];
__device__ float g_gs   [BB*DS];
__device__ float g_part1[MCH*BB*DM];
__device__ float g_part2[MCH*BB*DL];

// ---------------- multi-batch GEMV body: Y[b,m] = bias[m] + W[m,:]·X[b,:] ----------------
__device__ __forceinline__ void gemvA_body(int mblk, const float* __restrict__ W,
                                           const float* __restrict__ X, int ldx4,
                                           const float* __restrict__ bias,
                                           float* __restrict__ Y, int M, int D)
{
    int m = mblk * 8 + (threadIdx.x >> 5);
    int lane = threadIdx.x & 31;
    if (m >= M) return;
    const float4* w4 = (const float4*)(W + (size_t)m * D);
    const float4* x4 = (const float4*)X;
    int D4 = D >> 2;
    float acc[BB];
#pragma unroll
    for (int b = 0; b < BB; b++) acc[b] = 0.f;
    for (int f = lane; f < D4; f += 32) {
        float4 w = w4[f];
#pragma unroll
        for (int b = 0; b < BB; b++) {
            float4 x = x4[(size_t)b * ldx4 + f];
            acc[b] += w.x*x.x + w.y*x.y + w.z*x.z + w.w*x.w;
        }
    }
#pragma unroll
    for (int b = 0; b < BB; b++) {
        float v = acc[b];
#pragma unroll
        for (int o = 16; o; o >>= 1) v += __shfl_xor_sync(~0u, v, o);
        if (lane == 0) Y[(size_t)b * M + m] = v + (bias ? bias[m] : 0.f);
    }
}

// generic wrapper (epilogue launches)
__global__ __launch_bounds__(256) void gemvA_kernel(
    const float* __restrict__ W, const float* __restrict__ X, int ldx4,
    const float* __restrict__ bias, float* __restrict__ Y, int M, int D)
{
    gemvA_body(blockIdx.x, W, X, ldx4, bias, Y, M, D);
}

// stage1: csp (A, 64 blocks) + cmp (B, 128 blocks)
__global__ __launch_bounds__(256) void stage1_kernel(
    const float* __restrict__ f_s_w, const float* __restrict__ x2, const float* __restrict__ f_s_b,
    const float* __restrict__ f_m_w, const float* __restrict__ x1, const float* __restrict__ f_m_b)
{
    if (blockIdx.x < 64)
        gemvA_body(blockIdx.x, f_s_w, x2, (NL * DS) / 4, f_s_b, g_csp, DM, DS);
    else
        gemvA_body(blockIdx.x - 64, f_m_w, x1, ((NM + 1) * DM) / 4, f_m_b, g_cmp, DL, DM);
}

// stage2: q1 (64 blocks) + q2 (128 blocks)
__global__ __launch_bounds__(256) void stage2_kernel(
    const float* __restrict__ Wq1, const float* __restrict__ Wq2)
{
    if (blockIdx.x < 64)
        gemvA_body(blockIdx.x, Wq1, g_csp, DM / 4, nullptr, g_q1, DM, DM);
    else
        gemvA_body(blockIdx.x - 64, Wq2, g_cmp, DL / 4, nullptr, g_q2, DL, DL);
}

// ---------------- transposed GEMV partials ----------------
__device__ __forceinline__ void gemvBpart_body(int dx, int my, const float* __restrict__ W,
                                               const float* __restrict__ X,
                                               float* __restrict__ part, int M, int D)
{
    int d = dx * 256 + threadIdx.x;
    int rows = M / MCH;                 // 16 or 32
    int m0 = my * rows;
    __shared__ float q[BB * 32];
    for (int idx = threadIdx.x; idx < BB * rows; idx += 256) {
        int bb = idx / rows, mm = idx - bb * rows;
        q[bb * rows + mm] = X[(size_t)bb * M + m0 + mm];
    }
    __syncthreads();
    float acc[BB];
#pragma unroll
    for (int b = 0; b < BB; b++) acc[b] = 0.f;
    for (int mm = 0; mm < rows; mm++) {
        float w = W[(size_t)(m0 + mm) * D + d];
#pragma unroll
        for (int b = 0; b < BB; b++) acc[b] += w * q[b * rows + mm];
    }
#pragma unroll
    for (int b = 0; b < BB; b++)
        part[((size_t)my * BB + b) * D + d] = acc[b];
}

// stage3: qk1 partials (A: 2x32=64 blocks) + qk2 partials (B: 4x32=128)
__global__ __launch_bounds__(256) void stage3_kernel(
    const float* __restrict__ Wk1, const float* __restrict__ Wk2)
{
    if (blockIdx.x < 64)
        gemvBpart_body(blockIdx.x & 1, blockIdx.x >> 1, Wk1, g_q1, g_part1, DM, DM);
    else {
        int id = blockIdx.x - 64;
        gemvBpart_body(id & 3, id >> 2, Wk2, g_q2, g_part2, DL, DL);
    }
}

__device__ __forceinline__ void gemvBred_body(int t, const float* __restrict__ part,
                                              float* __restrict__ Y, int D)
{
    int b = t / D, d = t - b * D;
    float acc = 0.f;
#pragma unroll
    for (int c = 0; c < MCH; c++) acc += part[((size_t)c * BB + b) * D + d];
    Y[t] = acc;
}

// stage4: reduce qk1 (32 blocks) + qk2 (64 blocks)
__global__ __launch_bounds__(256) void stage4_kernel()
{
    if (blockIdx.x < 32)
        gemvBred_body(blockIdx.x * 256 + threadIdx.x, g_part1, g_qk1, DM);
    else
        gemvBred_body((blockIdx.x - 32) * 256 + threadIdx.x, g_part2, g_qk2, DL);
}

// ---------------- att1 scores over p_m ----------------
__global__ __launch_bounds__(256) void score1_kernel(const float* __restrict__ x1)
{
    int gw = (blockIdx.x * blockDim.x + threadIdx.x) >> 5;
    int lane = threadIdx.x & 31;
    int b = gw >> 10, k = gw & 1023;
    const float4* row = (const float4*)(x1 + ((size_t)b * (NM + 1) + 1 + k) * DM);
    const float4* qk  = (const float4*)(g_qk1 + (size_t)b * DM);
    float s = 0.f;
#pragma unroll
    for (int j = 0; j < 4; j++) {
        float4 v = row[lane + 32 * j];
        float4 q = qk [lane + 32 * j];
        s += v.x*q.x + v.y*q.y + v.z*q.z + v.w*q.w;
    }
#pragma unroll
    for (int o = 16; o; o >>= 1) s += __shfl_xor_sync(~0u, s, o);
    if (!lane) g_sc1[(size_t)b * (NM + 1) + 1 + k] = s * (1.f / 22.f);
}

// ---------------- softmax att1 (scores O(0.1) -> no max subtraction needed) ----------------
__global__ __launch_bounds__(256) void soft1_kernel()
{
    int b = blockIdx.x, t = threadIdx.x;
    __shared__ float red[256];
    __shared__ float ex[NM + 1];
    __shared__ float s0sh;
    float p = 0.f;
    for (int i = t; i < DM; i += 256) p += g_csp[b * DM + i] * g_qk1[b * DM + i];
    red[t] = p; __syncthreads();
    for (int s = 128; s; s >>= 1) { if (t < s) red[t] += red[t + s]; __syncthreads(); }
    if (t == 0) s0sh = red[0] * (1.f / 22.f);
    __syncthreads();
    float zp = 0.f;
    for (int i = t; i < NM + 1; i += 256) {
        float s = (i == 0) ? s0sh : g_sc1[b * (NM + 1) + i];
        float e = __expf(s);
        ex[i] = e; zp += e;
    }
    red[t] = zp; __syncthreads();
    for (int s = 128; s; s >>= 1) { if (t < s) red[t] += red[t + s]; __syncthreads(); }
    float inv = 1.f / red[0];
    for (int i = t; i < NM + 1; i += 256) g_att1s[b * (NM + 1) + i] = ex[i] * inv;
}

// ---------------- att1 projection ----------------
__global__ __launch_bounds__(256) void proj_kernel(
    const float* __restrict__ proj_w, const float* __restrict__ proj_b)
{
    __shared__ float att[8 * (NM + 1)];
    int bg = blockIdx.y;
    for (int idx = threadIdx.x; idx < 8 * (NM + 1); idx += 256) {
        int bb = idx / (NM + 1), i = idx - bb * (NM + 1);
        att[idx] = g_att1s[(size_t)(bg * 8 + bb) * (NM + 1) + i];
    }
    __syncthreads();
    int j = blockIdx.x * 8 + (threadIdx.x >> 5);
    int lane = threadIdx.x & 31;
    if (j >= NKV) return;
    const float* wrow = proj_w + (size_t)j * (NM + 1);
    float acc[8] = {0,0,0,0,0,0,0,0};
    for (int i = lane; i < NM + 1; i += 32) {
        float w = wrow[i];
#pragma unroll
        for (int bb = 0; bb < 8; bb++) acc[bb] += w * att[bb * (NM + 1) + i];
    }
#pragma unroll
    for (int bb = 0; bb < 8; bb++) {
        float v = acc[bb];
#pragma unroll
        for (int o = 16; o; o >>= 1) v += __shfl_xor_sync(~0u, v, o);
        if (!lane) g_a1p[(size_t)(bg * 8 + bb) * NKV + j] = v + proj_b[j];
    }
}

// ---------------- fused x0 pass: smem-staged, column-sliced, 2 phases ----------------
__global__ __launch_bounds__(256) void big2_kernel(const float* __restrict__ x0)
{
    extern __shared__ float4 vbuf[];        // [CROWS][256] float4 = 64 KB
    __shared__ float scp[CROWS][9];
    __shared__ float w1s[CROWS], w2s[CROWS];
    int b = blockIdx.y;
    int t = threadIdx.x, warp = t >> 5, lane = t & 31;
    float4 q = ((const float4*)(g_qk2 + (size_t)b * DL))[t];
    float4 aE = make_float4(0.f,0.f,0.f,0.f), aA = make_float4(0.f,0.f,0.f,0.f);
    float zsum = 0.f;
    int base_row = blockIdx.x * (CPB * CROWS);

    for (int c = 0; c < CPB; c++) {
        int k0 = base_row + c * CROWS;
        int rc = NL - k0;
        if (rc <= 0) break;
        if (rc > CROWS) rc = CROWS;
        const float4* rbase = (const float4*)(x0 + ((size_t)b * NL + k0) * DL) + t;
        // pass1: gmem -> smem + partial dot per warp slice
#pragma unroll
        for (int r = 0; r < CROWS; r++) {
            if (r < rc) {
                float4 v = rbase[(size_t)r * 256];
                vbuf[r * 256 + t] = v;
                float d = v.x*q.x + v.y*q.y + v.z*q.z + v.w*q.w;
#pragma unroll
                for (int o = 16; o; o >>= 1) d += __shfl_xor_sync(~0u, d, o);
                if (lane == 0) scp[r][warp] = d;
            }
        }
        __syncthreads();
        // weights: one warp combines per-row partials
        if (warp == 0) {
            float w2 = 0.f, w1 = 0.f;
            if (lane < rc) {
                float s = 0.f;
#pragma unroll
                for (int j = 0; j < 8; j++) s += scp[lane][j];
                w2 = __expf(s * (1.f / 32.f));
                w1 = g_a1p[(size_t)b * NKV + 1 + k0 + lane];
            }
            if (lane < CROWS) { w2s[lane] = w2; w1s[lane] = w1; }
            float z = w2;
#pragma unroll
            for (int o = 16; o; o >>= 1) z += __shfl_xor_sync(~0u, z, o);
            if (lane == 0) zsum += z;
        }
        __syncthreads();
        // pass2: weighted accumulation from smem
        for (int r = 0; r < rc; r++) {
            float4 v = vbuf[r * 256 + t];
            float w2 = w2s[r], w1 = w1s[r];
            aE.x += w2*v.x; aE.y += w2*v.y; aE.z += w2*v.z; aE.w += w2*v.w;
            aA.x += w1*v.x; aA.y += w1*v.y; aA.z += w1*v.z; aA.w += w1*v.w;
        }
        __syncthreads();
    }
    ((float4*)(g_PE + ((size_t)b * BCH + blockIdx.x) * DL))[t] = aE;
    ((float4*)(g_PA + ((size_t)b * BCH + blockIdx.x) * DL))[t] = aA;
    if (warp == 0 && lane == 0) g_PZ[b * BCH + blockIdx.x] = zsum;
}

// ---------------- combine partials -> u[b,d] ----------------
__global__ __launch_bounds__(1024) void u_kernel()
{
    int b = blockIdx.x, d = threadIdx.x;
    __shared__ float red[1024];
    __shared__ float zsh;
    float cmp = g_cmp[b * DL + d];
    float qk  = g_qk2[b * DL + d];
    red[d] = cmp * qk; __syncthreads();
    for (int s = 512; s; s >>= 1) { if (d < s) red[d] += red[d + s]; __syncthreads(); }
    float s2 = red[0] * (1.f / 32.f);
    float ecls = __expf(s2);
    if (d == 0) {
        float z = ecls;
        for (int c = 0; c < BCH; c++) z += g_PZ[b * BCH + c];
        zsh = z;
    }
    __syncthreads();
    float e = 0.f, a = 0.f;
    for (int c = 0; c < BCH; c++) {
        e += g_PE[((size_t)b * BCH + c) * DL + d];
        a += g_PA[((size_t)b * BCH + c) * DL + d];
    }
    float a1p0 = g_a1p[(size_t)b * NKV];
    g_u[b * DL + d] = 0.3f * (a1p0 * cmp + a) + 0.7f * (ecls * cmp + e) / zsh;
}

// ---------------- broadcast g_s to all 4097 output rows ----------------
__global__ __launch_bounds__(256) void write_kernel(float* __restrict__ out)
{
    int b = blockIdx.y;
    int g = threadIdx.x >> 6, l = threadIdx.x & 63;
    float4 val = ((const float4*)(g_gs + b * DS))[l];
    int base = blockIdx.x * 32;
    float4* ob = (float4*)out + (size_t)b * NL * 64;
    int lim = base + 32; if (lim > NL) lim = NL;
    for (int r = base + g; r < lim; r += 4)
        ob[(size_t)r * 64 + l] = val;
}

// ---------------- launch ----------------
extern "C" void kernel_launch(void* const* d_in, const int* in_sizes, int n_in,
                              void* d_out, int out_size)
{
    const float* x0     = (const float*)d_in[0];
    const float* x1     = (const float*)d_in[1];
    const float* x2     = (const float*)d_in[2];
    const float* f_s_w  = (const float*)d_in[3];
    const float* f_s_b  = (const float*)d_in[4];
    const float* f_m_w  = (const float*)d_in[5];
    const float* f_m_b  = (const float*)d_in[6];
    const float* Wq1    = (const float*)d_in[7];
    const float* Wk1    = (const float*)d_in[8];
    const float* Wq2    = (const float*)d_in[9];
    const float* Wk2    = (const float*)d_in[10];
    const float* Wv     = (const float*)d_in[11];
    const float* proj_w = (const float*)d_in[12];
    const float* proj_b = (const float*)d_in[13];
    const float* gs_w   = (const float*)d_in[14];
    const float* gs_b   = (const float*)d_in[15];

    static int smem_set = 0;
    if (!smem_set) {
        cudaFuncSetAttribute(big2_kernel, cudaFuncAttributeMaxDynamicSharedMemorySize, 65536);
        smem_set = 1;
    }

    float *p_u, *p_outv, *p_gs;
    cudaGetSymbolAddress((void**)&p_u,    g_u);
    cudaGetSymbolAddress((void**)&p_outv, g_outv);
    cudaGetSymbolAddress((void**)&p_gs,   g_gs);

    // merged small-branch chain
    stage1_kernel<<<192, 256>>>(f_s_w, x2, f_s_b, f_m_w, x1, f_m_b);
    stage2_kernel<<<192, 256>>>(Wq1, Wq2);
    stage3_kernel<<<192, 256>>>(Wk1, Wk2);
    stage4_kernel<<<96, 256>>>();

    // att1 branch
    score1_kernel<<<(BB * NM) / 8, 256>>>(x1);
    soft1_kernel<<<BB, 256>>>();
    proj_kernel<<<dim3((NKV + 7) / 8, 2), 256>>>(proj_w, proj_b);

    // fused att2 + weighted-value pass over x0
    big2_kernel<<<dim3(BCH, BB), 256, 65536>>>(x0);
    u_kernel<<<BB, 1024>>>();

    // epilogue: out = Wv·u ; g_s = gs_w·out + gs_b ; broadcast
    gemvA_kernel<<<128, 256>>>(Wv, p_u, DL / 4, nullptr, p_outv, DL, DL);
    gemvA_kernel<<<32, 256>>>(gs_w, p_outv, DL / 4, gs_b, p_gs, DS, DL);
    write_kernel<<<dim3((NL + 31) / 32, BB), 256>>>((float*)d_out);
}

// round 4
// speedup vs baseline: 1.0299x; 1.0299x over previous
#include <cuda_runtime.h>

// Problem constants
#define BB 16
#define NL 4097          // x0 rows per batch
#define NM 1024          // p_m rows
#define DS 256
#define DM 512
#define DL 1024
#define NKV 4098         // cls + NL
#define NCHUNK 65        // ceil(4097/64) for big kernel
#define MCH 32           // m-chunks for transposed gemv

// ---------------- device scratch ----------------
__device__ float g_csp  [BB*DM];
__device__ float g_qk1  [BB*DM];
__device__ float g_cmp  [BB*DL];
__device__ float g_qk2  [BB*DL];
__device__ float g_sc1  [BB*(NM+1)];
__device__ float g_a1p  [BB*NKV];
__device__ float g_PE   [BB*NCHUNK*DL];
__device__ float g_PA   [BB*NCHUNK*DL];
__device__ float g_PZ   [BB*NCHUNK];
__device__ float g_u    [BB*DL];
__device__ float g_outv [BB*DL];
__device__ float g_gs   [BB*DS];
__device__ float g_part1[MCH*BB*DM];
__device__ float g_part2[MCH*BB*DL];

// ---------------- multi-batch GEMV body: Y[b,m] = bias[m] + W[m,:]·X[b,:] ----------------
__device__ __forceinline__ void gemvA_body(int mblk, const float* __restrict__ W,
                                           const float* __restrict__ X, int ldx4,
                                           const float* __restrict__ bias,
                                           float* __restrict__ Y, int M, int D)
{
    int m = mblk * 8 + (threadIdx.x >> 5);
    int lane = threadIdx.x & 31;
    if (m >= M) return;
    const float4* w4 = (const float4*)(W + (size_t)m * D);
    const float4* x4 = (const float4*)X;
    int D4 = D >> 2;
    float acc[BB];
#pragma unroll
    for (int b = 0; b < BB; b++) acc[b] = 0.f;
    for (int f = lane; f < D4; f += 32) {
        float4 w = w4[f];
#pragma unroll
        for (int b = 0; b < BB; b++) {
            float4 x = x4[(size_t)b * ldx4 + f];
            acc[b] += w.x*x.x + w.y*x.y + w.z*x.z + w.w*x.w;
        }
    }
#pragma unroll
    for (int b = 0; b < BB; b++) {
        float v = acc[b];
#pragma unroll
        for (int o = 16; o; o >>= 1) v += __shfl_xor_sync(~0u, v, o);
        if (lane == 0) Y[(size_t)b * M + m] = v + (bias ? bias[m] : 0.f);
    }
}

__global__ __launch_bounds__(256) void gemvA_kernel(
    const float* __restrict__ W, const float* __restrict__ X, int ldx4,
    const float* __restrict__ bias, float* __restrict__ Y, int M, int D)
{
    gemvA_body(blockIdx.x, W, X, ldx4, bias, Y, M, D);
}

// stage1: csp (64 blocks) + cmp (128 blocks)
__global__ __launch_bounds__(256) void stage1_kernel(
    const float* __restrict__ f_s_w, const float* __restrict__ x2, const float* __restrict__ f_s_b,
    const float* __restrict__ f_m_w, const float* __restrict__ x1, const float* __restrict__ f_m_b)
{
    if (blockIdx.x < 64)
        gemvA_body(blockIdx.x, f_s_w, x2, (NL * DS) / 4, f_s_b, g_csp, DM, DS);
    else
        gemvA_body(blockIdx.x - 64, f_m_w, x1, ((NM + 1) * DM) / 4, f_m_b, g_cmp, DL, DM);
}

// ---------------- stage23: inline q = Wq·clsproj, then transposed-gemv partials ----------------
// blocks [0,32):  qk1, rows=16, D=DM  | blocks [32,64): qk2, rows=32, D=DL
__global__ __launch_bounds__(256) void stage23_kernel(
    const float* __restrict__ Wq1, const float* __restrict__ Wk1,
    const float* __restrict__ Wq2, const float* __restrict__ Wk2)
{
    __shared__ float q[BB * 32];
    int t = threadIdx.x;
    if (blockIdx.x < MCH) {
        int my = blockIdx.x, m0 = my * 16;
        {   // compute q1 slice: 256 (b,mm) pairs
            int bb = t & 15, mm = t >> 4;
            const float4* w4 = (const float4*)(Wq1 + (size_t)(m0 + mm) * DM);
            const float4* x4 = (const float4*)(g_csp + (size_t)bb * DM);
            float acc = 0.f;
#pragma unroll 4
            for (int f = 0; f < DM / 4; f++) {
                float4 w = w4[f], x = x4[f];
                acc += w.x*x.x + w.y*x.y + w.z*x.z + w.w*x.w;
            }
            q[bb * 16 + mm] = acc;
        }
        __syncthreads();
        float accd[2][BB];
#pragma unroll
        for (int j = 0; j < 2; j++)
#pragma unroll
            for (int b = 0; b < BB; b++) accd[j][b] = 0.f;
        for (int mm = 0; mm < 16; mm++) {
            float w0 = Wk1[(size_t)(m0 + mm) * DM + t];
            float w1 = Wk1[(size_t)(m0 + mm) * DM + t + 256];
#pragma unroll
            for (int b = 0; b < BB; b++) {
                float qq = q[b * 16 + mm];
                accd[0][b] += w0 * qq;
                accd[1][b] += w1 * qq;
            }
        }
#pragma unroll
        for (int j = 0; j < 2; j++)
#pragma unroll
            for (int b = 0; b < BB; b++)
                g_part1[((size_t)my * BB + b) * DM + t + 256 * j] = accd[j][b];
    } else {
        int my = blockIdx.x - MCH, m0 = my * 32;
#pragma unroll
        for (int i = 0; i < 2; i++) {   // 512 (b,mm) pairs, 2 per thread
            int p = t + 256 * i;
            int bb = p & 15, mm = p >> 4;
            const float4* w4 = (const float4*)(Wq2 + (size_t)(m0 + mm) * DL);
            const float4* x4 = (const float4*)(g_cmp + (size_t)bb * DL);
            float acc = 0.f;
#pragma unroll 4
            for (int f = 0; f < DL / 4; f++) {
                float4 w = w4[f], x = x4[f];
                acc += w.x*x.x + w.y*x.y + w.z*x.z + w.w*x.w;
            }
            q[bb * 32 + mm] = acc;
        }
        __syncthreads();
        float accd[4][BB];
#pragma unroll
        for (int j = 0; j < 4; j++)
#pragma unroll
            for (int b = 0; b < BB; b++) accd[j][b] = 0.f;
        for (int mm = 0; mm < 32; mm++) {
            float w0 = Wk2[(size_t)(m0 + mm) * DL + t];
            float w1 = Wk2[(size_t)(m0 + mm) * DL + t + 256];
            float w2 = Wk2[(size_t)(m0 + mm) * DL + t + 512];
            float w3 = Wk2[(size_t)(m0 + mm) * DL + t + 768];
#pragma unroll
            for (int b = 0; b < BB; b++) {
                float qq = q[b * 32 + mm];
                accd[0][b] += w0 * qq; accd[1][b] += w1 * qq;
                accd[2][b] += w2 * qq; accd[3][b] += w3 * qq;
            }
        }
#pragma unroll
        for (int j = 0; j < 4; j++)
#pragma unroll
            for (int b = 0; b < BB; b++)
                g_part2[((size_t)my * BB + b) * DL + t + 256 * j] = accd[j][b];
    }
}

__device__ __forceinline__ void gemvBred_body(int t, const float* __restrict__ part,
                                              float* __restrict__ Y, int D)
{
    int b = t / D, d = t - b * D;
    float acc = 0.f;
#pragma unroll
    for (int c = 0; c < MCH; c++) acc += part[((size_t)c * BB + b) * D + d];
    Y[t] = acc;
}

// stage4: reduce qk1 (32 blocks) + qk2 (64 blocks)
__global__ __launch_bounds__(256) void stage4_kernel()
{
    if (blockIdx.x < 32)
        gemvBred_body(blockIdx.x * 256 + threadIdx.x, g_part1, g_qk1, DM);
    else
        gemvBred_body((blockIdx.x - 32) * 256 + threadIdx.x, g_part2, g_qk2, DL);
}

// ---------------- att1 scores over p_m ----------------
__global__ __launch_bounds__(256) void score1_kernel(const float* __restrict__ x1)
{
    int gw = (blockIdx.x * blockDim.x + threadIdx.x) >> 5;
    int lane = threadIdx.x & 31;
    int b = gw >> 10, k = gw & 1023;
    const float4* row = (const float4*)(x1 + ((size_t)b * (NM + 1) + 1 + k) * DM);
    const float4* qk  = (const float4*)(g_qk1 + (size_t)b * DM);
    float s = 0.f;
#pragma unroll
    for (int j = 0; j < 4; j++) {
        float4 v = row[lane + 32 * j];
        float4 q = qk [lane + 32 * j];
        s += v.x*q.x + v.y*q.y + v.z*q.z + v.w*q.w;
    }
#pragma unroll
    for (int o = 16; o; o >>= 1) s += __shfl_xor_sync(~0u, s, o);
    if (!lane) g_sc1[(size_t)b * (NM + 1) + 1 + k] = s * (1.f / 22.f);
}

// ---------------- proj2: inline softmax (unnormalized exp + fold 1/Z) + projection ----------------
__global__ __launch_bounds__(256) void proj2_kernel(
    const float* __restrict__ proj_w, const float* __restrict__ proj_b)
{
    __shared__ float att[8 * (NM + 1)];
    __shared__ float zinv[8];
    int bg = blockIdx.y;
    int warp = threadIdx.x >> 5, lane = threadIdx.x & 31;
    {   // cls score s0, warp w -> batch bg*8+w
        int b = bg * 8 + warp;
        float p = 0.f;
        for (int i = lane; i < DM; i += 32) p += g_csp[b * DM + i] * g_qk1[b * DM + i];
#pragma unroll
        for (int o = 16; o; o >>= 1) p += __shfl_xor_sync(~0u, p, o);
        if (!lane) att[warp * (NM + 1)] = p * (1.f / 22.f);
    }
    __syncthreads();
    for (int idx = threadIdx.x; idx < 8 * (NM + 1); idx += 256) {
        int bb = idx / (NM + 1), i = idx - bb * (NM + 1);
        float s = (i == 0) ? att[idx] : g_sc1[(size_t)(bg * 8 + bb) * (NM + 1) + i];
        att[idx] = __expf(s);
    }
    __syncthreads();
    {   // per-batch Z, warp w -> batch w
        float z = 0.f;
        for (int i = lane; i < NM + 1; i += 32) z += att[warp * (NM + 1) + i];
#pragma unroll
        for (int o = 16; o; o >>= 1) z += __shfl_xor_sync(~0u, z, o);
        if (!lane) zinv[warp] = 1.f / z;
    }
    __syncthreads();
    int j = blockIdx.x * 8 + warp;
    if (j >= NKV) return;
    const float* wrow = proj_w + (size_t)j * (NM + 1);
    float acc[8] = {0,0,0,0,0,0,0,0};
    for (int i = lane; i < NM + 1; i += 32) {
        float w = wrow[i];
#pragma unroll
        for (int bb = 0; bb < 8; bb++) acc[bb] += w * att[bb * (NM + 1) + i];
    }
#pragma unroll
    for (int bb = 0; bb < 8; bb++) {
        float v = acc[bb];
#pragma unroll
        for (int o = 16; o; o >>= 1) v += __shfl_xor_sync(~0u, v, o);
        if (!lane) g_a1p[(size_t)(bg * 8 + bb) * NKV + j] = v * zinv[bb] + proj_b[j];
    }
}

// ---------------- fused x0 pass (R2 register version) ----------------
__global__ __launch_bounds__(256) void big_kernel(const float* __restrict__ x0)
{
    int b = blockIdx.y, chunk = blockIdx.x;
    int t = threadIdx.x, warp = t >> 5, lane = t & 31;
    __shared__ float4 qk2s[256];
    __shared__ float4 Es[256], As[256];
    __shared__ float Zs[8];
    qk2s[t] = ((const float4*)(g_qk2 + (size_t)b * DL))[t];
    Es[t] = make_float4(0.f, 0.f, 0.f, 0.f);
    As[t] = make_float4(0.f, 0.f, 0.f, 0.f);
    __syncthreads();

    float4 aE[8], aA[8];
#pragma unroll
    for (int j = 0; j < 8; j++) { aE[j] = make_float4(0,0,0,0); aA[j] = make_float4(0,0,0,0); }
    float zacc = 0.f;
    int k0 = chunk * 64;
    for (int r = warp; r < 64; r += 8) {
        int k = k0 + r;
        if (k >= NL) break;
        const float4* row = (const float4*)(x0 + ((size_t)b * NL + k) * DL);
        float4 v[8];
#pragma unroll
        for (int j = 0; j < 8; j++) v[j] = row[lane + 32 * j];
        float s = 0.f;
#pragma unroll
        for (int j = 0; j < 8; j++) {
            float4 q = qk2s[lane + 32 * j];
            s += v[j].x*q.x + v[j].y*q.y + v[j].z*q.z + v[j].w*q.w;
        }
#pragma unroll
        for (int o = 16; o; o >>= 1) s += __shfl_xor_sync(~0u, s, o);
        float w2 = __expf(s * (1.f / 32.f));
        float w1 = g_a1p[(size_t)b * NKV + k + 1];
        zacc += w2;
#pragma unroll
        for (int j = 0; j < 8; j++) {
            aE[j].x += w2 * v[j].x; aE[j].y += w2 * v[j].y; aE[j].z += w2 * v[j].z; aE[j].w += w2 * v[j].w;
            aA[j].x += w1 * v[j].x; aA[j].y += w1 * v[j].y; aA[j].z += w1 * v[j].z; aA[j].w += w1 * v[j].w;
        }
    }
    for (int w = 0; w < 8; w++) {
        if (warp == w) {
#pragma unroll
            for (int j = 0; j < 8; j++) {
                int idx = lane + 32 * j;
                float4 e = Es[idx];
                e.x += aE[j].x; e.y += aE[j].y; e.z += aE[j].z; e.w += aE[j].w;
                Es[idx] = e;
                float4 a = As[idx];
                a.x += aA[j].x; a.y += aA[j].y; a.z += aA[j].z; a.w += aA[j].w;
                As[idx] = a;
            }
            if (lane == 0) Zs[w] = zacc;
        }
        __syncthreads();
    }
    ((float4*)(g_PE + ((size_t)b * NCHUNK + chunk) * DL))[t] = Es[t];
    ((float4*)(g_PA + ((size_t)b * NCHUNK + chunk) * DL))[t] = As[t];
    if (t == 0) {
        float z = 0.f;
#pragma unroll
        for (int w = 0; w < 8; w++) z += Zs[w];
        g_PZ[b * NCHUNK + chunk] = z;
    }
}

// ---------------- combine partials -> u[b,d] ----------------
__global__ __launch_bounds__(1024) void u_kernel()
{
    int b = blockIdx.x, d = threadIdx.x;
    __shared__ float red[1024];
    __shared__ float zsh;
    float cmp = g_cmp[b * DL + d];
    float qk  = g_qk2[b * DL + d];
    red[d] = cmp * qk; __syncthreads();
    for (int s = 512; s; s >>= 1) { if (d < s) red[d] += red[d + s]; __syncthreads(); }
    float s2 = red[0] * (1.f / 32.f);
    float ecls = __expf(s2);
    if (d == 0) {
        float z = ecls;
        for (int c = 0; c < NCHUNK; c++) z += g_PZ[b * NCHUNK + c];
        zsh = z;
    }
    __syncthreads();
    float e = 0.f, a = 0.f;
    for (int c = 0; c < NCHUNK; c++) {
        e += g_PE[((size_t)b * NCHUNK + c) * DL + d];
        a += g_PA[((size_t)b * NCHUNK + c) * DL + d];
    }
    float a1p0 = g_a1p[(size_t)b * NKV];
    g_u[b * DL + d] = 0.3f * (a1p0 * cmp + a) + 0.7f * (ecls * cmp + e) / zsh;
}

// ---------------- broadcast g_s to all 4097 output rows ----------------
__global__ __launch_bounds__(256) void write_kernel(float* __restrict__ out)
{
    int b = blockIdx.y;
    int g = threadIdx.x >> 6, l = threadIdx.x & 63;
    float4 val = ((const float4*)(g_gs + b * DS))[l];
    int base = blockIdx.x * 32;
    float4* ob = (float4*)out + (size_t)b * NL * 64;
    int lim = base + 32; if (lim > NL) lim = NL;
    for (int r = base + g; r < lim; r += 4)
        ob[(size_t)r * 64 + l] = val;
}

// ---------------- launch ----------------
extern "C" void kernel_launch(void* const* d_in, const int* in_sizes, int n_in,
                              void* d_out, int out_size)
{
    const float* x0     = (const float*)d_in[0];
    const float* x1     = (const float*)d_in[1];
    const float* x2     = (const float*)d_in[2];
    const float* f_s_w  = (const float*)d_in[3];
    const float* f_s_b  = (const float*)d_in[4];
    const float* f_m_w  = (const float*)d_in[5];
    const float* f_m_b  = (const float*)d_in[6];
    const float* Wq1    = (const float*)d_in[7];
    const float* Wk1    = (const float*)d_in[8];
    const float* Wq2    = (const float*)d_in[9];
    const float* Wk2    = (const float*)d_in[10];
    const float* Wv     = (const float*)d_in[11];
    const float* proj_w = (const float*)d_in[12];
    const float* proj_b = (const float*)d_in[13];
    const float* gs_w   = (const float*)d_in[14];
    const float* gs_b   = (const float*)d_in[15];

    float *p_u, *p_outv, *p_gs;
    cudaGetSymbolAddress((void**)&p_u,    g_u);
    cudaGetSymbolAddress((void**)&p_outv, g_outv);
    cudaGetSymbolAddress((void**)&p_gs,   g_gs);

    stage1_kernel<<<192, 256>>>(f_s_w, x2, f_s_b, f_m_w, x1, f_m_b);
    stage23_kernel<<<64, 256>>>(Wq1, Wk1, Wq2, Wk2);
    stage4_kernel<<<96, 256>>>();

    score1_kernel<<<(BB * NM) / 8, 256>>>(x1);
    proj2_kernel<<<dim3((NKV + 7) / 8, 2), 256>>>(proj_w, proj_b);

    big_kernel<<<dim3(NCHUNK, BB), 256>>>(x0);
    u_kernel<<<BB, 1024>>>();

    gemvA_kernel<<<128, 256>>>(Wv, p_u, DL / 4, nullptr, p_outv, DL, DL);
    gemvA_kernel<<<32, 256>>>(gs_w, p_outv, DL / 4, gs_b, p_gs, DS, DL);
    write_kernel<<<dim3((NL + 31) / 32, BB), 256>>>((float*)d_out);
}

// round 5
// speedup vs baseline: 1.1671x; 1.1333x over previous
#include <cuda_runtime.h>

// Problem constants
#define BB 16
#define NL 4097          // x0 rows per batch
#define NM 1024          // p_m rows
#define DS 256
#define DM 512
#define DL 1024
#define NKV 4098         // cls + NL
#define NCHUNK 64        // big covers 64*64 = 4096 rows; row 4096 handled in u_kernel
#define MCH 32           // m-chunks for transposed gemv

// ---------------- device scratch ----------------
__device__ float g_csp  [BB*DM];
__device__ float g_q1   [BB*DM];
__device__ float g_qk1  [BB*DM];
__device__ float g_cmp  [BB*DL];
__device__ float g_q2   [BB*DL];
__device__ float g_qk2  [BB*DL];
__device__ float g_sc1  [BB*(NM+1)];
__device__ float g_att1s[BB*(NM+1)];
__device__ float g_a1p  [BB*NKV];
__device__ float g_PE   [BB*NCHUNK*DL];
__device__ float g_PA   [BB*NCHUNK*DL];
__device__ float g_PZ   [BB*NCHUNK];
__device__ float g_u    [BB*DL];
__device__ float g_outv [BB*DL];
__device__ float g_gs   [BB*DS];
__device__ float g_part1[MCH*BB*DM];
__device__ float g_part2[MCH*BB*DL];

// ---------------- multi-batch GEMV body: Y[b,m] = bias[m] + W[m,:]·X[b,:] ----------------
__device__ __forceinline__ void gemvA_body(int mblk, const float* __restrict__ W,
                                           const float* __restrict__ X, int ldx4,
                                           const float* __restrict__ bias,
                                           float* __restrict__ Y, int M, int D)
{
    int m = mblk * 8 + (threadIdx.x >> 5);
    int lane = threadIdx.x & 31;
    if (m >= M) return;
    const float4* w4 = (const float4*)(W + (size_t)m * D);
    const float4* x4 = (const float4*)X;
    int D4 = D >> 2;
    float acc[BB];
#pragma unroll
    for (int b = 0; b < BB; b++) acc[b] = 0.f;
    for (int f = lane; f < D4; f += 32) {
        float4 w = w4[f];
#pragma unroll
        for (int b = 0; b < BB; b++) {
            float4 x = x4[(size_t)b * ldx4 + f];
            acc[b] += w.x*x.x + w.y*x.y + w.z*x.z + w.w*x.w;
        }
    }
#pragma unroll
    for (int b = 0; b < BB; b++) {
        float v = acc[b];
#pragma unroll
        for (int o = 16; o; o >>= 1) v += __shfl_xor_sync(~0u, v, o);
        if (lane == 0) Y[(size_t)b * M + m] = v + (bias ? bias[m] : 0.f);
    }
}

__global__ __launch_bounds__(256) void gemvA_kernel(
    const float* __restrict__ W, const float* __restrict__ X, int ldx4,
    const float* __restrict__ bias, float* __restrict__ Y, int M, int D)
{
    gemvA_body(blockIdx.x, W, X, ldx4, bias, Y, M, D);
}

// stage1: csp (64 blocks) + cmp (128 blocks)
__global__ __launch_bounds__(256) void stage1_kernel(
    const float* __restrict__ f_s_w, const float* __restrict__ x2, const float* __restrict__ f_s_b,
    const float* __restrict__ f_m_w, const float* __restrict__ x1, const float* __restrict__ f_m_b)
{
    if (blockIdx.x < 64)
        gemvA_body(blockIdx.x, f_s_w, x2, (NL * DS) / 4, f_s_b, g_csp, DM, DS);
    else
        gemvA_body(blockIdx.x - 64, f_m_w, x1, ((NM + 1) * DM) / 4, f_m_b, g_cmp, DL, DM);
}

// stage2: q1 (64 blocks) + q2 (128 blocks), coalesced warp-per-row
__global__ __launch_bounds__(256) void stage2_kernel(
    const float* __restrict__ Wq1, const float* __restrict__ Wq2)
{
    if (blockIdx.x < 64)
        gemvA_body(blockIdx.x, Wq1, g_csp, DM / 4, nullptr, g_q1, DM, DM);
    else
        gemvA_body(blockIdx.x - 64, Wq2, g_cmp, DL / 4, nullptr, g_q2, DL, DL);
}

// ---------------- transposed GEMV partials (R2 coalesced form) ----------------
__device__ __forceinline__ void gemvBpart_body(int dx, int my, const float* __restrict__ W,
                                               const float* __restrict__ X,
                                               float* __restrict__ part, int M, int D)
{
    int d = dx * 256 + threadIdx.x;
    int rows = M / MCH;                 // 16 or 32
    int m0 = my * rows;
    __shared__ float q[BB * 32];
    for (int idx = threadIdx.x; idx < BB * rows; idx += 256) {
        int bb = idx / rows, mm = idx - bb * rows;
        q[bb * rows + mm] = X[(size_t)bb * M + m0 + mm];
    }
    __syncthreads();
    float acc[BB];
#pragma unroll
    for (int b = 0; b < BB; b++) acc[b] = 0.f;
    for (int mm = 0; mm < rows; mm++) {
        float w = W[(size_t)(m0 + mm) * D + d];
#pragma unroll
        for (int b = 0; b < BB; b++) acc[b] += w * q[b * rows + mm];
    }
#pragma unroll
    for (int b = 0; b < BB; b++)
        part[((size_t)my * BB + b) * D + d] = acc[b];
}

// stage3: qk1 partials (64 blocks) + qk2 partials (128 blocks)
__global__ __launch_bounds__(256) void stage3_kernel(
    const float* __restrict__ Wk1, const float* __restrict__ Wk2)
{
    if (blockIdx.x < 64)
        gemvBpart_body(blockIdx.x & 1, blockIdx.x >> 1, Wk1, g_q1, g_part1, DM, DM);
    else {
        int id = blockIdx.x - 64;
        gemvBpart_body(id & 3, id >> 2, Wk2, g_q2, g_part2, DL, DL);
    }
}

__device__ __forceinline__ void gemvBred_body(int t, const float* __restrict__ part,
                                              float* __restrict__ Y, int D)
{
    int b = t / D, d = t - b * D;
    float acc = 0.f;
#pragma unroll
    for (int c = 0; c < MCH; c++) acc += part[((size_t)c * BB + b) * D + d];
    Y[t] = acc;
}

// stage4: reduce qk1 (32 blocks) + qk2 (64 blocks)
__global__ __launch_bounds__(256) void stage4_kernel()
{
    if (blockIdx.x < 32)
        gemvBred_body(blockIdx.x * 256 + threadIdx.x, g_part1, g_qk1, DM);
    else
        gemvBred_body((blockIdx.x - 32) * 256 + threadIdx.x, g_part2, g_qk2, DL);
}

// ---------------- att1 scores over p_m: 4 rows per warp ----------------
__global__ __launch_bounds__(256) void score1_kernel(const float* __restrict__ x1)
{
    int gw = (blockIdx.x * 256 + threadIdx.x) >> 5;
    int lane = threadIdx.x & 31;
    int rr = gw * 4;
    int b = rr >> 10, k0 = rr & 1023;          // 4 consecutive rows share b
    const float4* qk = (const float4*)(g_qk1 + (size_t)b * DM);
    float4 q[4];
#pragma unroll
    for (int j = 0; j < 4; j++) q[j] = qk[lane + 32 * j];
#pragma unroll
    for (int i = 0; i < 4; i++) {
        const float4* row = (const float4*)(x1 + ((size_t)b * (NM + 1) + 1 + k0 + i) * DM);
        float s = 0.f;
#pragma unroll
        for (int j = 0; j < 4; j++) {
            float4 v = row[lane + 32 * j];
            s += v.x*q[j].x + v.y*q[j].y + v.z*q[j].z + v.w*q[j].w;
        }
#pragma unroll
        for (int o = 16; o; o >>= 1) s += __shfl_xor_sync(~0u, s, o);
        if (!lane) g_sc1[(size_t)b * (NM + 1) + 1 + k0 + i] = s * (1.f / 22.f);
    }
}

// ---------------- softmax att1 (scores O(0.1) -> no max subtraction needed) ----------------
__global__ __launch_bounds__(256) void soft1_kernel()
{
    int b = blockIdx.x, t = threadIdx.x;
    __shared__ float red[256];
    __shared__ float ex[NM + 1];
    __shared__ float s0sh;
    float p = 0.f;
    for (int i = t; i < DM; i += 256) p += g_csp[b * DM + i] * g_qk1[b * DM + i];
    red[t] = p; __syncthreads();
    for (int s = 128; s; s >>= 1) { if (t < s) red[t] += red[t + s]; __syncthreads(); }
    if (t == 0) s0sh = red[0] * (1.f / 22.f);
    __syncthreads();
    float zp = 0.f;
    for (int i = t; i < NM + 1; i += 256) {
        float s = (i == 0) ? s0sh : g_sc1[b * (NM + 1) + i];
        float e = __expf(s);
        ex[i] = e; zp += e;
    }
    red[t] = zp; __syncthreads();
    for (int s = 128; s; s >>= 1) { if (t < s) red[t] += red[t + s]; __syncthreads(); }
    float inv = 1.f / red[0];
    for (int i = t; i < NM + 1; i += 256) g_att1s[b * (NM + 1) + i] = ex[i] * inv;
}

// ---------------- att1 projection: single pass over proj_w, all 16 batches ----------------
__global__ __launch_bounds__(256) void proj_kernel(
    const float* __restrict__ proj_w, const float* __restrict__ proj_b)
{
    extern __shared__ float att[];             // [BB * (NM+1)] = 65568 B
    for (int idx = threadIdx.x; idx < BB * (NM + 1); idx += 256) {
        int bb = idx / (NM + 1), i = idx - bb * (NM + 1);
        att[idx] = g_att1s[(size_t)bb * (NM + 1) + i];
    }
    __syncthreads();
    int j = blockIdx.x * 8 + (threadIdx.x >> 5);
    int lane = threadIdx.x & 31;
    if (j >= NKV) return;
    const float* wrow = proj_w + (size_t)j * (NM + 1);
    float acc[BB];
#pragma unroll
    for (int bb = 0; bb < BB; bb++) acc[bb] = 0.f;
    for (int i = lane; i < NM + 1; i += 32) {
        float w = wrow[i];
#pragma unroll
        for (int bb = 0; bb < BB; bb++) acc[bb] += w * att[bb * (NM + 1) + i];
    }
#pragma unroll
    for (int bb = 0; bb < BB; bb++) {
        float v = acc[bb];
#pragma unroll
        for (int o = 16; o; o >>= 1) v += __shfl_xor_sync(~0u, v, o);
        if (!lane) g_a1p[(size_t)bb * NKV + j] = v + proj_b[j];
    }
}

// ---------------- fused x0 pass: 64 full rows per chunk, no bounds checks ----------------
__global__ __launch_bounds__(256) void big_kernel(const float* __restrict__ x0)
{
    int b = blockIdx.y, chunk = blockIdx.x;
    int t = threadIdx.x, warp = t >> 5, lane = t & 31;
    __shared__ float4 qk2s[256];
    __shared__ float4 Es[256], As[256];
    __shared__ float Zs[8];
    qk2s[t] = ((const float4*)(g_qk2 + (size_t)b * DL))[t];
    Es[t] = make_float4(0.f, 0.f, 0.f, 0.f);
    As[t] = make_float4(0.f, 0.f, 0.f, 0.f);
    __syncthreads();

    float4 aE[8], aA[8];
#pragma unroll
    for (int j = 0; j < 8; j++) { aE[j] = make_float4(0,0,0,0); aA[j] = make_float4(0,0,0,0); }
    float zacc = 0.f;
    int k0 = chunk * 64 + warp;
#pragma unroll 2
    for (int rr = 0; rr < 8; rr++) {
        int k = k0 + rr * 8;
        const float4* row = (const float4*)(x0 + ((size_t)b * NL + k) * DL);
        float4 v[8];
#pragma unroll
        for (int j = 0; j < 8; j++) v[j] = row[lane + 32 * j];
        float s = 0.f;
#pragma unroll
        for (int j = 0; j < 8; j++) {
            float4 q = qk2s[lane + 32 * j];
            s += v[j].x*q.x + v[j].y*q.y + v[j].z*q.z + v[j].w*q.w;
        }
#pragma unroll
        for (int o = 16; o; o >>= 1) s += __shfl_xor_sync(~0u, s, o);
        float w2 = __expf(s * (1.f / 32.f));
        float w1 = g_a1p[(size_t)b * NKV + k + 1];
        zacc += w2;
#pragma unroll
        for (int j = 0; j < 8; j++) {
            aE[j].x += w2 * v[j].x; aE[j].y += w2 * v[j].y; aE[j].z += w2 * v[j].z; aE[j].w += w2 * v[j].w;
            aA[j].x += w1 * v[j].x; aA[j].y += w1 * v[j].y; aA[j].z += w1 * v[j].z; aA[j].w += w1 * v[j].w;
        }
    }
    for (int w = 0; w < 8; w++) {
        if (warp == w) {
#pragma unroll
            for (int j = 0; j < 8; j++) {
                int idx = lane + 32 * j;
                float4 e = Es[idx];
                e.x += aE[j].x; e.y += aE[j].y; e.z += aE[j].z; e.w += aE[j].w;
                Es[idx] = e;
                float4 a = As[idx];
                a.x += aA[j].x; a.y += aA[j].y; a.z += aA[j].z; a.w += aA[j].w;
                As[idx] = a;
            }
            if (lane == 0) Zs[w] = zacc;
        }
        __syncthreads();
    }
    ((float4*)(g_PE + ((size_t)b * NCHUNK + chunk) * DL))[t] = Es[t];
    ((float4*)(g_PA + ((size_t)b * NCHUNK + chunk) * DL))[t] = As[t];
    if (t == 0) {
        float z = 0.f;
#pragma unroll
        for (int w = 0; w < 8; w++) z += Zs[w];
        g_PZ[b * NCHUNK + chunk] = z;
    }
}

// ---------------- combine partials + cls row + last p_l row -> u[b,d] ----------------
__global__ __launch_bounds__(1024) void u_kernel(const float* __restrict__ x0)
{
    int b = blockIdx.x, d = threadIdx.x;
    __shared__ float red[1024];
    __shared__ float zsh, wl2sh;
    float cmp = g_cmp[b * DL + d];
    float qk  = g_qk2[b * DL + d];
    float xlast = x0[((size_t)b * NL + NL - 1) * DL + d];
    // two dots: cls (cmp·qk) and last row (xlast·qk)
    red[d] = cmp * qk; __syncthreads();
    for (int s = 512; s; s >>= 1) { if (d < s) red[d] += red[d + s]; __syncthreads(); }
    float ecls = __expf(red[0] * (1.f / 32.f));
    __syncthreads();
    red[d] = xlast * qk; __syncthreads();
    for (int s = 512; s; s >>= 1) { if (d < s) red[d] += red[d + s]; __syncthreads(); }
    if (d == 0) {
        float wl2 = __expf(red[0] * (1.f / 32.f));
        float z = ecls + wl2;
        for (int c = 0; c < NCHUNK; c++) z += g_PZ[b * NCHUNK + c];
        zsh = z; wl2sh = wl2;
    }
    __syncthreads();
    float e = 0.f, a = 0.f;
    for (int c = 0; c < NCHUNK; c++) {
        e += g_PE[((size_t)b * NCHUNK + c) * DL + d];
        a += g_PA[((size_t)b * NCHUNK + c) * DL + d];
    }
    float a1p0 = g_a1p[(size_t)b * NKV];
    float a1pl = g_a1p[(size_t)b * NKV + NKV - 1];
    e += wl2sh * xlast;
    a += a1pl * xlast;
    g_u[b * DL + d] = 0.3f * (a1p0 * cmp + a) + 0.7f * (ecls * cmp + e) / zsh;
}

// ---------------- broadcast g_s to all 4097 output rows ----------------
__global__ __launch_bounds__(256) void write_kernel(float* __restrict__ out)
{
    int b = blockIdx.y;
    int g = threadIdx.x >> 6, l = threadIdx.x & 63;
    float4 val = ((const float4*)(g_gs + b * DS))[l];
    int base = blockIdx.x * 32;
    float4* ob = (float4*)out + (size_t)b * NL * 64;
    int lim = base + 32; if (lim > NL) lim = NL;
    for (int r = base + g; r < lim; r += 4)
        ob[(size_t)r * 64 + l] = val;
}

// ---------------- launch ----------------
extern "C" void kernel_launch(void* const* d_in, const int* in_sizes, int n_in,
                              void* d_out, int out_size)
{
    const float* x0     = (const float*)d_in[0];
    const float* x1     = (const float*)d_in[1];
    const float* x2     = (const float*)d_in[2];
    const float* f_s_w  = (const float*)d_in[3];
    const float* f_s_b  = (const float*)d_in[4];
    const float* f_m_w  = (const float*)d_in[5];
    const float* f_m_b  = (const float*)d_in[6];
    const float* Wq1    = (const float*)d_in[7];
    const float* Wk1    = (const float*)d_in[8];
    const float* Wq2    = (const float*)d_in[9];
    const float* Wk2    = (const float*)d_in[10];
    const float* Wv     = (const float*)d_in[11];
    const float* proj_w = (const float*)d_in[12];
    const float* proj_b = (const float*)d_in[13];
    const float* gs_w   = (const float*)d_in[14];
    const float* gs_b   = (const float*)d_in[15];

    cudaFuncSetAttribute(proj_kernel, cudaFuncAttributeMaxDynamicSharedMemorySize,
                         BB * (NM + 1) * 4);

    float *p_u, *p_outv, *p_gs;
    cudaGetSymbolAddress((void**)&p_u,    g_u);
    cudaGetSymbolAddress((void**)&p_outv, g_outv);
    cudaGetSymbolAddress((void**)&p_gs,   g_gs);

    stage1_kernel<<<192, 256>>>(f_s_w, x2, f_s_b, f_m_w, x1, f_m_b);
    stage2_kernel<<<192, 256>>>(Wq1, Wq2);
    stage3_kernel<<<192, 256>>>(Wk1, Wk2);
    stage4_kernel<<<96, 256>>>();

    score1_kernel<<<(BB * NM) / 32, 256>>>(x1);
    soft1_kernel<<<BB, 256>>>();
    proj_kernel<<<(NKV + 7) / 8, 256, BB * (NM + 1) * 4>>>(proj_w, proj_b);

    big_kernel<<<dim3(NCHUNK, BB), 256>>>(x0);
    u_kernel<<<BB, 1024>>>(x0);

    gemvA_kernel<<<128, 256>>>(Wv, p_u, DL / 4, nullptr, p_outv, DL, DL);
    gemvA_kernel<<<32, 256>>>(gs_w, p_outv, DL / 4, gs_b, p_gs, DS, DL);
    write_kernel<<<dim3((NL + 31) / 32, BB), 256>>>((float*)d_out);
}

// round 6
// speedup vs baseline: 1.3616x; 1.1666x over previous
#include <cuda_runtime.h>

// Problem constants
#define BB 16
#define NL 4097          // x0 rows per batch
#define NM 1024          // p_m rows
#define DS 256
#define DM 512
#define DL 1024
#define NKV 4098         // cls + NL
#define NCHUNK 64        // big covers 64*64 = 4096 rows; row 4096 handled in u_kernel
#define MCH 32           // m-chunks for transposed gemv

// ---------------- device scratch ----------------
__device__ float g_csp  [BB*DM];
__device__ float g_q1   [BB*DM];
__device__ float g_qk1  [BB*DM];
__device__ float g_cmp  [BB*DL];
__device__ float g_q2   [BB*DL];
__device__ float g_qk2  [BB*DL];
__device__ float g_sc1  [BB*(NM+1)];
__device__ float g_att1s[BB*(NM+1)];
__device__ float g_a1p  [BB*NKV];
__device__ float g_PE   [BB*NCHUNK*DL];
__device__ float g_PA   [BB*NCHUNK*DL];
__device__ float g_PZ   [BB*NCHUNK];
__device__ float g_u    [BB*DL];
__device__ float g_outv [BB*DL];
__device__ float g_gs   [BB*DS];
__device__ float g_part1[MCH*BB*DM];
__device__ float g_part2[MCH*BB*DL];

// ---------------- multi-batch GEMV: Y[b,m] = bias[m] + W[m,:]·X[b,:] ----------------
__global__ __launch_bounds__(256) void gemvA_kernel(
    const float* __restrict__ W, const float* __restrict__ X, int ldx4,
    const float* __restrict__ bias, float* __restrict__ Y, int M, int D)
{
    int m = blockIdx.x * 8 + (threadIdx.x >> 5);
    int lane = threadIdx.x & 31;
    if (m >= M) return;
    const float4* w4 = (const float4*)(W + (size_t)m * D);
    const float4* x4 = (const float4*)X;
    int D4 = D >> 2;
    float acc[BB];
#pragma unroll
    for (int b = 0; b < BB; b++) acc[b] = 0.f;
    for (int f = lane; f < D4; f += 32) {
        float4 w = w4[f];
#pragma unroll
        for (int b = 0; b < BB; b++) {
            float4 x = x4[(size_t)b * ldx4 + f];
            acc[b] += w.x*x.x + w.y*x.y + w.z*x.z + w.w*x.w;
        }
    }
#pragma unroll
    for (int b = 0; b < BB; b++) {
        float v = acc[b];
#pragma unroll
        for (int o = 16; o; o >>= 1) v += __shfl_xor_sync(~0u, v, o);
        if (lane == 0) Y[(size_t)b * M + m] = v + (bias ? bias[m] : 0.f);
    }
}

// ---------------- transposed GEMV partials: part[my][b][d] ----------------
__global__ __launch_bounds__(256) void gemvB_kernel(
    const float* __restrict__ W, const float* __restrict__ X,
    float* __restrict__ part, int M, int D)
{
    int d = blockIdx.x * 256 + threadIdx.x;
    int rows = M / MCH;                 // 16 or 32
    int m0 = blockIdx.y * rows;
    __shared__ float q[BB * 32];
    for (int idx = threadIdx.x; idx < BB * rows; idx += 256) {
        int bb = idx / rows, mm = idx - bb * rows;
        q[bb * rows + mm] = X[(size_t)bb * M + m0 + mm];
    }
    __syncthreads();
    float acc[BB];
#pragma unroll
    for (int b = 0; b < BB; b++) acc[b] = 0.f;
    for (int mm = 0; mm < rows; mm++) {
        float w = W[(size_t)(m0 + mm) * D + d];
#pragma unroll
        for (int b = 0; b < BB; b++) acc[b] += w * q[b * rows + mm];
    }
#pragma unroll
    for (int b = 0; b < BB; b++)
        part[((size_t)blockIdx.y * BB + b) * D + d] = acc[b];
}

__global__ __launch_bounds__(256) void gemvBred_kernel(
    const float* __restrict__ part, float* __restrict__ Y, int D)
{
    int t = blockIdx.x * 256 + threadIdx.x;
    int b = t / D, d = t - b * D;
    float acc = 0.f;
#pragma unroll
    for (int c = 0; c < MCH; c++) acc += part[((size_t)c * BB + b) * D + d];
    Y[t] = acc;
}

// ---------------- att1 scores over p_m: 4 rows per warp ----------------
__global__ __launch_bounds__(256) void score1_kernel(const float* __restrict__ x1)
{
    int gw = (blockIdx.x * 256 + threadIdx.x) >> 5;
    int lane = threadIdx.x & 31;
    int rr = gw * 4;
    int b = rr >> 10, k0 = rr & 1023;
    const float4* qk = (const float4*)(g_qk1 + (size_t)b * DM);
    float4 q[4];
#pragma unroll
    for (int j = 0; j < 4; j++) q[j] = qk[lane + 32 * j];
#pragma unroll
    for (int i = 0; i < 4; i++) {
        const float4* row = (const float4*)(x1 + ((size_t)b * (NM + 1) + 1 + k0 + i) * DM);
        float s = 0.f;
#pragma unroll
        for (int j = 0; j < 4; j++) {
            float4 v = __ldcs(row + lane + 32 * j);
            s += v.x*q[j].x + v.y*q[j].y + v.z*q[j].z + v.w*q[j].w;
        }
#pragma unroll
        for (int o = 16; o; o >>= 1) s += __shfl_xor_sync(~0u, s, o);
        if (!lane) g_sc1[(size_t)b * (NM + 1) + 1 + k0 + i] = s * (1.f / 22.f);
    }
}

// ---------------- softmax att1 (scores O(0.1) -> no max subtraction needed) ----------------
__global__ __launch_bounds__(256) void soft1_kernel()
{
    int b = blockIdx.x, t = threadIdx.x;
    __shared__ float red[256];
    __shared__ float ex[NM + 1];
    __shared__ float s0sh;
    float p = 0.f;
    for (int i = t; i < DM; i += 256) p += g_csp[b * DM + i] * g_qk1[b * DM + i];
    red[t] = p; __syncthreads();
    for (int s = 128; s; s >>= 1) { if (t < s) red[t] += red[t + s]; __syncthreads(); }
    if (t == 0) s0sh = red[0] * (1.f / 22.f);
    __syncthreads();
    float zp = 0.f;
    for (int i = t; i < NM + 1; i += 256) {
        float s = (i == 0) ? s0sh : g_sc1[b * (NM + 1) + i];
        float e = __expf(s);
        ex[i] = e; zp += e;
    }
    red[t] = zp; __syncthreads();
    for (int s = 128; s; s >>= 1) { if (t < s) red[t] += red[t + s]; __syncthreads(); }
    float inv = 1.f / red[0];
    for (int i = t; i < NM + 1; i += 256) g_att1s[b * (NM + 1) + i] = ex[i] * inv;
}

// ---------------- att1 projection: single pass over proj_w, all 16 batches ----------------
__global__ __launch_bounds__(256) void proj_kernel(
    const float* __restrict__ proj_w, const float* __restrict__ proj_b)
{
    extern __shared__ float att[];             // [BB * (NM+1)] = 65568 B
    for (int idx = threadIdx.x; idx < BB * (NM + 1); idx += 256) {
        int bb = idx / (NM + 1), i = idx - bb * (NM + 1);
        att[idx] = g_att1s[(size_t)bb * (NM + 1) + i];
    }
    __syncthreads();
    int j = blockIdx.x * 8 + (threadIdx.x >> 5);
    int lane = threadIdx.x & 31;
    if (j >= NKV) return;
    const float* wrow = proj_w + (size_t)j * (NM + 1);
    float acc[BB];
#pragma unroll
    for (int bb = 0; bb < BB; bb++) acc[bb] = 0.f;
    for (int i = lane; i < NM + 1; i += 32) {
        float w = __ldcs(wrow + i);
#pragma unroll
        for (int bb = 0; bb < BB; bb++) acc[bb] += w * att[bb * (NM + 1) + i];
    }
#pragma unroll
    for (int bb = 0; bb < BB; bb++) {
        float v = acc[bb];
#pragma unroll
        for (int o = 16; o; o >>= 1) v += __shfl_xor_sync(~0u, v, o);
        if (!lane) g_a1p[(size_t)bb * NKV + j] = v + proj_b[j];
    }
}

// ---------------- fused x0 pass: 64 full rows per chunk ----------------
__global__ __launch_bounds__(256) void big_kernel(const float* __restrict__ x0)
{
    int b = blockIdx.y, chunk = blockIdx.x;
    int t = threadIdx.x, warp = t >> 5, lane = t & 31;
    __shared__ float4 qk2s[256];
    __shared__ float4 Es[256], As[256];
    __shared__ float Zs[8];
    qk2s[t] = ((const float4*)(g_qk2 + (size_t)b * DL))[t];
    Es[t] = make_float4(0.f, 0.f, 0.f, 0.f);
    As[t] = make_float4(0.f, 0.f, 0.f, 0.f);
    __syncthreads();

    float4 aE[8], aA[8];
#pragma unroll
    for (int j = 0; j < 8; j++) { aE[j] = make_float4(0,0,0,0); aA[j] = make_float4(0,0,0,0); }
    float zacc = 0.f;
    int k0 = chunk * 64 + warp;
#pragma unroll 2
    for (int rr = 0; rr < 8; rr++) {
        int k = k0 + rr * 8;
        const float4* row = (const float4*)(x0 + ((size_t)b * NL + k) * DL);
        float4 v[8];
#pragma unroll
        for (int j = 0; j < 8; j++) v[j] = __ldcs(row + lane + 32 * j);
        float s = 0.f;
#pragma unroll
        for (int j = 0; j < 8; j++) {
            float4 q = qk2s[lane + 32 * j];
            s += v[j].x*q.x + v[j].y*q.y + v[j].z*q.z + v[j].w*q.w;
        }
#pragma unroll
        for (int o = 16; o; o >>= 1) s += __shfl_xor_sync(~0u, s, o);
        float w2 = __expf(s * (1.f / 32.f));
        float w1 = g_a1p[(size_t)b * NKV + k + 1];
        zacc += w2;
#pragma unroll
        for (int j = 0; j < 8; j++) {
            aE[j].x += w2 * v[j].x; aE[j].y += w2 * v[j].y; aE[j].z += w2 * v[j].z; aE[j].w += w2 * v[j].w;
            aA[j].x += w1 * v[j].x; aA[j].y += w1 * v[j].y; aA[j].z += w1 * v[j].z; aA[j].w += w1 * v[j].w;
        }
    }
    for (int w = 0; w < 8; w++) {
        if (warp == w) {
#pragma unroll
            for (int j = 0; j < 8; j++) {
                int idx = lane + 32 * j;
                float4 e = Es[idx];
                e.x += aE[j].x; e.y += aE[j].y; e.z += aE[j].z; e.w += aE[j].w;
                Es[idx] = e;
                float4 a = As[idx];
                a.x += aA[j].x; a.y += aA[j].y; a.z += aA[j].z; a.w += aA[j].w;
                As[idx] = a;
            }
            if (lane == 0) Zs[w] = zacc;
        }
        __syncthreads();
    }
    ((float4*)(g_PE + ((size_t)b * NCHUNK + chunk) * DL))[t] = Es[t];
    ((float4*)(g_PA + ((size_t)b * NCHUNK + chunk) * DL))[t] = As[t];
    if (t == 0) {
        float z = 0.f;
#pragma unroll
        for (int w = 0; w < 8; w++) z += Zs[w];
        g_PZ[b * NCHUNK + chunk] = z;
    }
}

// ---------------- combine partials + cls row + last p_l row -> u[b,d] ----------------
__global__ __launch_bounds__(1024) void u_kernel(const float* __restrict__ x0)
{
    int b = blockIdx.x, d = threadIdx.x;
    __shared__ float red[1024];
    __shared__ float zsh, wl2sh;
    float cmp = g_cmp[b * DL + d];
    float qk  = g_qk2[b * DL + d];
    float xlast = x0[((size_t)b * NL + NL - 1) * DL + d];
    red[d] = cmp * qk; __syncthreads();
    for (int s = 512; s; s >>= 1) { if (d < s) red[d] += red[d + s]; __syncthreads(); }
    float ecls = __expf(red[0] * (1.f / 32.f));
    __syncthreads();
    red[d] = xlast * qk; __syncthreads();
    for (int s = 512; s; s >>= 1) { if (d < s) red[d] += red[d + s]; __syncthreads(); }
    if (d == 0) {
        float wl2 = __expf(red[0] * (1.f / 32.f));
        float z = ecls + wl2;
        for (int c = 0; c < NCHUNK; c++) z += g_PZ[b * NCHUNK + c];
        zsh = z; wl2sh = wl2;
    }
    __syncthreads();
    float e = 0.f, a = 0.f;
    for (int c = 0; c < NCHUNK; c++) {
        e += g_PE[((size_t)b * NCHUNK + c) * DL + d];
        a += g_PA[((size_t)b * NCHUNK + c) * DL + d];
    }
    float a1p0 = g_a1p[(size_t)b * NKV];
    float a1pl = g_a1p[(size_t)b * NKV + NKV - 1];
    e += wl2sh * xlast;
    a += a1pl * xlast;
    g_u[b * DL + d] = 0.3f * (a1p0 * cmp + a) + 0.7f * (ecls * cmp + e) / zsh;
}

// ---------------- broadcast g_s to all 4097 output rows ----------------
__global__ __launch_bounds__(256) void write_kernel(float* __restrict__ out)
{
    int b = blockIdx.y;
    int g = threadIdx.x >> 6, l = threadIdx.x & 63;
    float4 val = ((const float4*)(g_gs + b * DS))[l];
    int base = blockIdx.x * 32;
    float4* ob = (float4*)out + (size_t)b * NL * 64;
    int lim = base + 32; if (lim > NL) lim = NL;
    for (int r = base + g; r < lim; r += 4)
        __stcs(ob + (size_t)r * 64 + l, val);
}

// ---------------- launch: fork-join multi-stream capture ----------------
extern "C" void kernel_launch(void* const* d_in, const int* in_sizes, int n_in,
                              void* d_out, int out_size)
{
    const float* x0     = (const float*)d_in[0];
    const float* x1     = (const float*)d_in[1];
    const float* x2     = (const float*)d_in[2];
    const float* f_s_w  = (const float*)d_in[3];
    const float* f_s_b  = (const float*)d_in[4];
    const float* f_m_w  = (const float*)d_in[5];
    const float* f_m_b  = (const float*)d_in[6];
    const float* Wq1    = (const float*)d_in[7];
    const float* Wk1    = (const float*)d_in[8];
    const float* Wq2    = (const float*)d_in[9];
    const float* Wk2    = (const float*)d_in[10];
    const float* Wv     = (const float*)d_in[11];
    const float* proj_w = (const float*)d_in[12];
    const float* proj_b = (const float*)d_in[13];
    const float* gs_w   = (const float*)d_in[14];
    const float* gs_b   = (const float*)d_in[15];

    static cudaStream_t s1 = nullptr, s2 = nullptr;
    static cudaEvent_t evr = nullptr, ev1 = nullptr, ev2 = nullptr;
    if (!s1) {
        cudaStreamCreateWithFlags(&s1, cudaStreamNonBlocking);
        cudaStreamCreateWithFlags(&s2, cudaStreamNonBlocking);
        cudaEventCreateWithFlags(&evr, cudaEventDisableTiming);
        cudaEventCreateWithFlags(&ev1, cudaEventDisableTiming);
        cudaEventCreateWithFlags(&ev2, cudaEventDisableTiming);
        cudaFuncSetAttribute(proj_kernel, cudaFuncAttributeMaxDynamicSharedMemorySize,
                             BB * (NM + 1) * 4);
    }

    float *p_csp, *p_q1, *p_qk1, *p_cmp, *p_q2, *p_qk2, *p_u, *p_outv, *p_gs, *p_part1, *p_part2;
    cudaGetSymbolAddress((void**)&p_csp,   g_csp);
    cudaGetSymbolAddress((void**)&p_q1,    g_q1);
    cudaGetSymbolAddress((void**)&p_qk1,   g_qk1);
    cudaGetSymbolAddress((void**)&p_cmp,   g_cmp);
    cudaGetSymbolAddress((void**)&p_q2,    g_q2);
    cudaGetSymbolAddress((void**)&p_qk2,   g_qk2);
    cudaGetSymbolAddress((void**)&p_u,     g_u);
    cudaGetSymbolAddress((void**)&p_outv,  g_outv);
    cudaGetSymbolAddress((void**)&p_gs,    g_gs);
    cudaGetSymbolAddress((void**)&p_part1, g_part1);
    cudaGetSymbolAddress((void**)&p_part2, g_part2);

    // fork
    cudaEventRecord(evr, 0);
    cudaStreamWaitEvent(s1, evr, 0);
    cudaStreamWaitEvent(s2, evr, 0);

    // Branch 1 (att1 chain): csp -> q1 -> qk1 -> score1 -> soft1 -> proj
    gemvA_kernel<<<64, 256, 0, s1>>>(f_s_w, x2, (NL * DS) / 4, f_s_b, p_csp, DM, DS);
    gemvA_kernel<<<64, 256, 0, s1>>>(Wq1, p_csp, DM / 4, nullptr, p_q1, DM, DM);
    gemvB_kernel<<<dim3(2, MCH), 256, 0, s1>>>(Wk1, p_q1, p_part1, DM, DM);
    gemvBred_kernel<<<32, 256, 0, s1>>>(p_part1, p_qk1, DM);
    score1_kernel<<<(BB * NM) / 32, 256, 0, s1>>>(x1);
    soft1_kernel<<<BB, 256, 0, s1>>>();
    proj_kernel<<<(NKV + 7) / 8, 256, BB * (NM + 1) * 4, s1>>>(proj_w, proj_b);

    // Branch 2 (qk2 chain): cmp -> q2 -> qk2
    gemvA_kernel<<<128, 256, 0, s2>>>(f_m_w, x1, ((NM + 1) * DM) / 4, f_m_b, p_cmp, DL, DM);
    gemvA_kernel<<<128, 256, 0, s2>>>(Wq2, p_cmp, DL / 4, nullptr, p_q2, DL, DL);
    gemvB_kernel<<<dim3(4, MCH), 256, 0, s2>>>(Wk2, p_q2, p_part2, DL, DL);
    gemvBred_kernel<<<64, 256, 0, s2>>>(p_part2, p_qk2, DL);

    // join
    cudaEventRecord(ev1, s1);
    cudaEventRecord(ev2, s2);
    cudaStreamWaitEvent(0, ev1, 0);
    cudaStreamWaitEvent(0, ev2, 0);

    // main chain
    big_kernel<<<dim3(NCHUNK, BB), 256>>>(x0);
    u_kernel<<<BB, 1024>>>(x0);
    gemvA_kernel<<<128, 256>>>(Wv, p_u, DL / 4, nullptr, p_outv, DL, DL);
    gemvA_kernel<<<32, 256>>>(gs_w, p_outv, DL / 4, gs_b, p_gs, DS, DL);
    write_kernel<<<dim3((NL + 31) / 32, BB), 256>>>((float*)d_out);
}